// round 17
// baseline (speedup 1.0000x reference)
#include <cuda_runtime.h>
#include <cuda_bf16.h>
#include <cstdint>

// Problem constants (fixed by the dataset)
#define NNODES 100000
#define NEDGES 1600000
#define INC    500
#define HID    256
#define OUTC   40
#define KSTEPS 10
#define ALPHA  0.1f
#define LNEPS  1e-5f

#define SCAN_NB 98   // ceil(NNODES / 1024)
#define KP1 250      // INC/2 k-pairs
#define KP2 128      // HID/2 k-pairs

// ---------------- scratch (static device globals; no runtime allocation) ----
__device__ float g_h1[(size_t)NNODES * HID];
__device__ float g_h2[(size_t)NNODES * HID];
__device__ float g_h0[(size_t)NNODES * OUTC];
__device__ float g_p0[(size_t)NNODES * OUTC];
__device__ float g_p1[(size_t)NNODES * OUTC];
__device__ int   g_cnt[NNODES];                // zero at entry (invariant)
__device__ int   g_offs[NNODES + 1];
__device__ int   g_cur[NNODES];
__device__ float g_dinv[NNODES];
__device__ long long g_ew[NEDGES];             // packed (wt<<32 | src)
__device__ int   g_bsum[128];
__device__ int   g_boff[128];
// pre-split weights, [kpair][n] packed bf16x2 (hi, lo)
__device__ uint32_t g_w1h[KP1 * HID], g_w1l[KP1 * HID];
__device__ uint32_t g_w2h[KP2 * HID], g_w2l[KP2 * HID];
__device__ uint32_t g_w3h[KP2 * OUTC], g_w3l[KP2 * OUTC];

__device__ __forceinline__ float gelu_f(float t) {
    return 0.5f * t * (1.0f + erff(t * 0.70710678118654752f));
}

// HMMA m16n8k16 bf16 x bf16 -> fp32 accumulate
__device__ __forceinline__ void mma16816(float* d, const uint32_t* a,
                                         const uint32_t* b)
{
    asm volatile(
        "mma.sync.aligned.m16n8k16.row.col.f32.bf16.bf16.f32 "
        "{%0,%1,%2,%3}, {%4,%5,%6,%7}, {%8,%9}, {%0,%1,%2,%3};"
        : "+f"(d[0]), "+f"(d[1]), "+f"(d[2]), "+f"(d[3])
        : "r"(a[0]), "r"(a[1]), "r"(a[2]), "r"(a[3]), "r"(b[0]), "r"(b[1]));
}

__device__ __forceinline__ void split_pack(float v0, float v1,
                                           uint32_t& ph, uint32_t& pl)
{
    __nv_bfloat16 h0 = __float2bfloat16(v0);
    __nv_bfloat16 h1 = __float2bfloat16(v1);
    __nv_bfloat16 l0 = __float2bfloat16(v0 - __bfloat162float(h0));
    __nv_bfloat16 l1 = __float2bfloat16(v1 - __bfloat162float(h1));
    ph = ((uint32_t)__bfloat16_as_ushort(h1) << 16) | __bfloat16_as_ushort(h0);
    pl = ((uint32_t)__bfloat16_as_ushort(l1) << 16) | __bfloat16_as_ushort(l0);
}

// ---------------------------------------------------------------------------
// Pre-split a weight matrix W [2*KP, NDIM] into packed hi/lo [KP][NDIM].
// ---------------------------------------------------------------------------
template <int KP, int NDIM, int Sel>  // Sel: 0->w1, 1->w2, 2->w3
__global__ void wsplit_kernel(const float* __restrict__ W)
{
    uint32_t* __restrict__ oh = (Sel == 0) ? g_w1h : (Sel == 1) ? g_w2h : g_w3h;
    uint32_t* __restrict__ ol = (Sel == 0) ? g_w1l : (Sel == 1) ? g_w2l : g_w3l;
    int idx = blockIdx.x * blockDim.x + threadIdx.x;
    if (idx < KP * NDIM) {
        const int p = idx / NDIM, n = idx % NDIM;
        const float v0 = __ldg(&W[(size_t)(2 * p) * NDIM + n]);
        const float v1 = __ldg(&W[(size_t)(2 * p + 1) * NDIM + n]);
        split_pack(v0, v1, oh[idx], ol[idx]);
    }
}

// ===========================================================================
// bf16-split mma.sync MLP layer: out = LayerNorm(GELU(A @ W + b)).
// CTA: 64 rows x 256 cols, 8 warps in 2(M) x 4(N); warp tile 32 x 64.
// ===========================================================================
template <int KDIM, int InSel, int OutSel>
__global__ void __launch_bounds__(256) mlp_mma_kernel(
    const float* __restrict__ Aext,
    const float* __restrict__ bias, const float* __restrict__ gamma,
    const float* __restrict__ beta)
{
    constexpr int NCH = (KDIM + 31) / 32;
    constexpr int KPAIRS = KDIM / 2;
    const float* __restrict__ A   = (InSel == 0) ? Aext : (const float*)g_h1;
    float* __restrict__       out = (OutSel == 0) ? g_h1 : g_h2;
    const uint32_t* __restrict__ Wh = (InSel == 0) ? g_w1h : g_w2h;
    const uint32_t* __restrict__ Wl = (InSel == 0) ? g_w1l : g_w2l;

    __shared__ uint32_t sAh[64][18], sAl[64][18];
    __shared__ uint32_t sBh[256][18], sBl[256][18];

    const int tid  = threadIdx.x;
    const int wid  = tid >> 5;
    const int lane = tid & 31;
    const int g    = lane >> 2;
    const int tig  = lane & 3;
    const int wm   = wid >> 2;
    const int wn   = wid & 3;
    const int row0 = blockIdx.x * 64;

    float acc[2][8][4];
#pragma unroll
    for (int mt = 0; mt < 2; ++mt)
#pragma unroll
        for (int nt = 0; nt < 8; ++nt)
#pragma unroll
            for (int j = 0; j < 4; ++j) acc[mt][nt][j] = 0.0f;

    for (int c = 0; c < NCH; ++c) {
        const int k0 = c * 32;
        const int pb = c * 16;
#pragma unroll
        for (int idx = tid; idx < 64 * 16; idx += 256) {
            const int r = idx >> 4, p = idx & 15;
            const int k = k0 + 2 * p;
            const int gr = row0 + r;
            float v0 = 0.0f, v1 = 0.0f;
            if (gr < NNODES) {
                if (k < KDIM)     v0 = __ldg(&A[(size_t)gr * KDIM + k]);
                if (k + 1 < KDIM) v1 = __ldg(&A[(size_t)gr * KDIM + k + 1]);
            }
            split_pack(v0, v1, sAh[r][p], sAl[r][p]);
        }
#pragma unroll
        for (int idx = tid; idx < 16 * 256; idx += 256) {
            const int p = idx >> 8, n = idx & 255;
            const int gp = pb + p;
            uint32_t vh = 0, vl = 0;
            if (gp < KPAIRS) {
                vh = __ldg(&Wh[(size_t)gp * HID + n]);
                vl = __ldg(&Wl[(size_t)gp * HID + n]);
            }
            sBh[n][p] = vh;
            sBl[n][p] = vl;
        }
        __syncthreads();

#pragma unroll
        for (int s = 0; s < 2; ++s) {
            const int pb2 = s * 8;
            uint32_t ah[2][4], al[2][4];
#pragma unroll
            for (int mt = 0; mt < 2; ++mt) {
                const int rb = wm * 32 + mt * 16;
                ah[mt][0] = sAh[rb + g][pb2 + tig];
                ah[mt][1] = sAh[rb + g + 8][pb2 + tig];
                ah[mt][2] = sAh[rb + g][pb2 + tig + 4];
                ah[mt][3] = sAh[rb + g + 8][pb2 + tig + 4];
                al[mt][0] = sAl[rb + g][pb2 + tig];
                al[mt][1] = sAl[rb + g + 8][pb2 + tig];
                al[mt][2] = sAl[rb + g][pb2 + tig + 4];
                al[mt][3] = sAl[rb + g + 8][pb2 + tig + 4];
            }
#pragma unroll
            for (int nt = 0; nt < 8; ++nt) {
                const int nb = wn * 64 + nt * 8 + g;
                uint32_t bh[2] = { sBh[nb][pb2 + tig], sBh[nb][pb2 + tig + 4] };
                uint32_t bl[2] = { sBl[nb][pb2 + tig], sBl[nb][pb2 + tig + 4] };
#pragma unroll
                for (int mt = 0; mt < 2; ++mt) {
                    mma16816(acc[mt][nt], ah[mt], bh);
                    mma16816(acc[mt][nt], ah[mt], bl);
                    mma16816(acc[mt][nt], al[mt], bh);
                }
            }
        }
        __syncthreads();
    }

    // ---- epilogue: bias + exact GELU (in place) + per-row partial sums ----
    float s[2][2] = {{0.f, 0.f}, {0.f, 0.f}};
    float q[2][2] = {{0.f, 0.f}, {0.f, 0.f}};
#pragma unroll
    for (int mt = 0; mt < 2; ++mt)
#pragma unroll
        for (int nt = 0; nt < 8; ++nt)
#pragma unroll
            for (int h = 0; h < 2; ++h)
#pragma unroll
                for (int j = 0; j < 2; ++j) {
                    const int n = wn * 64 + nt * 8 + tig * 2 + j;
                    float t = gelu_f(acc[mt][nt][2 * h + j] + __ldg(&bias[n]));
                    acc[mt][nt][2 * h + j] = t;
                    s[mt][h] += t;
                    q[mt][h] += t * t;
                }
#pragma unroll
    for (int mt = 0; mt < 2; ++mt)
#pragma unroll
        for (int h = 0; h < 2; ++h) {
            s[mt][h] += __shfl_xor_sync(0xffffffffu, s[mt][h], 1);
            s[mt][h] += __shfl_xor_sync(0xffffffffu, s[mt][h], 2);
            q[mt][h] += __shfl_xor_sync(0xffffffffu, q[mt][h], 1);
            q[mt][h] += __shfl_xor_sync(0xffffffffu, q[mt][h], 2);
        }

    float* ps = (float*)sAh;        // [64 rows][4 warps]
    float* pq = ps + 256;
    if (tig == 0) {
#pragma unroll
        for (int mt = 0; mt < 2; ++mt)
#pragma unroll
            for (int h = 0; h < 2; ++h) {
                const int row = wm * 32 + mt * 16 + h * 8 + g;
                ps[row * 4 + wn] = s[mt][h];
                pq[row * 4 + wn] = q[mt][h];
            }
    }
    __syncthreads();

#pragma unroll
    for (int mt = 0; mt < 2; ++mt)
#pragma unroll
        for (int h = 0; h < 2; ++h) {
            const int row = wm * 32 + mt * 16 + h * 8 + g;
            const int gr  = row0 + row;
            const float st = ps[row * 4 + 0] + ps[row * 4 + 1] +
                             ps[row * 4 + 2] + ps[row * 4 + 3];
            const float qt = pq[row * 4 + 0] + pq[row * 4 + 1] +
                             pq[row * 4 + 2] + pq[row * 4 + 3];
            const float mu  = st * (1.0f / HID);
            const float var = qt * (1.0f / HID) - mu * mu;
            const float rst = rsqrtf(var + LNEPS);
            if (gr < NNODES) {
#pragma unroll
                for (int nt = 0; nt < 8; ++nt) {
                    const int n0 = wn * 64 + nt * 8 + tig * 2;
                    float y0 = (acc[mt][nt][2 * h + 0] - mu) * rst *
                                   __ldg(&gamma[n0]) + __ldg(&beta[n0]);
                    float y1 = (acc[mt][nt][2 * h + 1] - mu) * rst *
                                   __ldg(&gamma[n0 + 1]) + __ldg(&beta[n0 + 1]);
                    *(float2*)&out[(size_t)gr * HID + n0] = make_float2(y0, y1);
                }
            }
        }
}

// ===========================================================================
// GEMM3 via bf16-split mma: g_h0 = g_h2 [N,256] @ W3 [256,40] + b3.
// ===========================================================================
__global__ void __launch_bounds__(256) gemm3_mma_kernel(
    const float* __restrict__ bias)
{
    __shared__ uint32_t sAh[128][18], sAl[128][18];
    __shared__ uint32_t sBh[40][18],  sBl[40][18];

    const int tid  = threadIdx.x;
    const int wid  = tid >> 5;
    const int lane = tid & 31;
    const int g    = lane >> 2;
    const int tig  = lane & 3;
    const int row0 = blockIdx.x * 128;

    float acc[5][4];
#pragma unroll
    for (int nt = 0; nt < 5; ++nt)
#pragma unroll
        for (int j = 0; j < 4; ++j) acc[nt][j] = 0.0f;

    for (int c = 0; c < HID / 32; ++c) {
        const int k0 = c * 32;
        const int pb = c * 16;
#pragma unroll
        for (int idx = tid; idx < 128 * 16; idx += 256) {
            const int r = idx >> 4, p = idx & 15;
            const int k = k0 + 2 * p;
            const int gr = row0 + r;
            float v0 = 0.0f, v1 = 0.0f;
            if (gr < NNODES) {
                v0 = g_h2[(size_t)gr * HID + k];
                v1 = g_h2[(size_t)gr * HID + k + 1];
            }
            split_pack(v0, v1, sAh[r][p], sAl[r][p]);
        }
        for (int idx = tid; idx < 40 * 16; idx += 256) {
            const int n = idx / 16, p = idx & 15;
            sBh[n][p] = g_w3h[(size_t)(pb + p) * OUTC + n];
            sBl[n][p] = g_w3l[(size_t)(pb + p) * OUTC + n];
        }
        __syncthreads();

#pragma unroll
        for (int s = 0; s < 2; ++s) {
            const int pb2 = s * 8;
            const int rb = wid * 16;
            uint32_t ah[4], al[4];
            ah[0] = sAh[rb + g][pb2 + tig];
            ah[1] = sAh[rb + g + 8][pb2 + tig];
            ah[2] = sAh[rb + g][pb2 + tig + 4];
            ah[3] = sAh[rb + g + 8][pb2 + tig + 4];
            al[0] = sAl[rb + g][pb2 + tig];
            al[1] = sAl[rb + g + 8][pb2 + tig];
            al[2] = sAl[rb + g][pb2 + tig + 4];
            al[3] = sAl[rb + g + 8][pb2 + tig + 4];
#pragma unroll
            for (int nt = 0; nt < 5; ++nt) {
                const int nb = nt * 8 + g;
                uint32_t bh[2] = { sBh[nb][pb2 + tig], sBh[nb][pb2 + tig + 4] };
                uint32_t bl[2] = { sBl[nb][pb2 + tig], sBl[nb][pb2 + tig + 4] };
                mma16816(acc[nt], ah, bh);
                mma16816(acc[nt], ah, bl);
                mma16816(acc[nt], al, bh);
            }
        }
        __syncthreads();
    }

#pragma unroll
    for (int nt = 0; nt < 5; ++nt)
#pragma unroll
        for (int h = 0; h < 2; ++h) {
            const int gr = row0 + wid * 16 + h * 8 + g;
            const int n0 = nt * 8 + tig * 2;
            if (gr < NNODES) {
                float y0 = acc[nt][2 * h + 0] + __ldg(&bias[n0]);
                float y1 = acc[nt][2 * h + 1] + __ldg(&bias[n0 + 1]);
                *(float2*)&g_h0[(size_t)gr * OUTC + n0] = make_float2(y0, y1);
            }
        }
}

// ---------------------------------------------------------------------------
// Graph prep. edge_index int32 [2, E]: ei[0:E)=src, ei[E:2E)=dst.
// ---------------------------------------------------------------------------
__global__ void count_kernel(const int* __restrict__ ei)
{
    int e = blockIdx.x * blockDim.x + threadIdx.x;
    if (e < NEDGES) {
        unsigned c = (unsigned)ei[NEDGES + e];
        if (c < NNODES) atomicAdd(&g_cnt[c], 1);
    }
}

__global__ void dinv_kernel()
{
    int i = blockIdx.x * blockDim.x + threadIdx.x;
    if (i < NNODES) g_dinv[i] = rsqrtf(1.0f + (float)g_cnt[i]);
}

// parallel scan, phase A: per-block sums (1024 elems/block)
__global__ void __launch_bounds__(1024) scanA_kernel()
{
    const int idx = blockIdx.x * 1024 + threadIdx.x;
    int v = (idx < NNODES) ? g_cnt[idx] : 0;
#pragma unroll
    for (int o = 16; o >= 1; o >>= 1) v += __shfl_xor_sync(0xffffffffu, v, o);
    __shared__ int ws[32];
    if ((threadIdx.x & 31) == 0) ws[threadIdx.x >> 5] = v;
    __syncthreads();
    if (threadIdx.x < 32) {
        int t = ws[threadIdx.x];
#pragma unroll
        for (int o = 16; o >= 1; o >>= 1) t += __shfl_xor_sync(0xffffffffu, t, o);
        if (threadIdx.x == 0) g_bsum[blockIdx.x] = t;
    }
}

// phase B: exclusive scan of SCAN_NB block sums (one 128-thread block)
__global__ void scanB_kernel()
{
    const int t = threadIdx.x;
    const int lane = t & 31, w = t >> 5;
    int v = (t < SCAN_NB) ? g_bsum[t] : 0;
    int iv = v;
#pragma unroll
    for (int o = 1; o < 32; o <<= 1) {
        int n = __shfl_up_sync(0xffffffffu, iv, o);
        if (lane >= o) iv += n;
    }
    __shared__ int ws[4];
    if (lane == 31) ws[w] = iv;
    __syncthreads();
    int add = 0;
    for (int i = 0; i < w; ++i) add += ws[i];
    iv += add;
    if (t < SCAN_NB) g_boff[t] = iv - v;
    if (t == SCAN_NB - 1) g_offs[NNODES] = iv;
}

// phase C: block-local exclusive scan + global offset -> offs, cur
__global__ void __launch_bounds__(1024) scanC_kernel()
{
    const int idx = blockIdx.x * 1024 + threadIdx.x;
    const int lane = threadIdx.x & 31, w = threadIdx.x >> 5;
    int v = (idx < NNODES) ? g_cnt[idx] : 0;
    int iv = v;
#pragma unroll
    for (int o = 1; o < 32; o <<= 1) {
        int n = __shfl_up_sync(0xffffffffu, iv, o);
        if (lane >= o) iv += n;
    }
    __shared__ int ws[32];
    __shared__ int wo[32];
    if (lane == 31) ws[w] = iv;
    __syncthreads();
    if (threadIdx.x < 32) {
        int t2 = ws[threadIdx.x];
        int s2 = t2;
#pragma unroll
        for (int o = 1; o < 32; o <<= 1) {
            int n = __shfl_up_sync(0xffffffffu, s2, o);
            if (lane >= o) s2 += n;
        }
        wo[threadIdx.x] = s2 - t2;
    }
    __syncthreads();
    const int ex = g_boff[blockIdx.x] + wo[w] + (iv - v);
    if (idx < NNODES) {
        g_offs[idx] = ex;
        g_cur[idx]  = ex;
    }
}

__global__ void scatter_kernel(const int* __restrict__ ei)
{
    int e = blockIdx.x * blockDim.x + threadIdx.x;
    if (e < NEDGES) {
        unsigned r = (unsigned)ei[e];
        unsigned c = (unsigned)ei[NEDGES + e];
        if (r < NNODES && c < NNODES) {
            int p = atomicAdd(&g_cur[c], 1);
            const float wt = g_dinv[r] * g_dinv[c];
            g_ew[p] = ((long long)(unsigned long long)__float_as_uint(wt) << 32) |
                      (long long)r;
        }
    }
}

// restore the g_cnt==0 invariant for the next launch (runs at END)
__global__ void zero_cnt_kernel()
{
    int i = blockIdx.x * blockDim.x + threadIdx.x;
    if (i < NNODES) g_cnt[i] = 0;
}

// ---------------------------------------------------------------------------
// APPNP propagation v3: one warp per node, 6 edges per loop step.
// Lanes 0-5 fetch packed meta; 3 groups of 10 lanes each service 2 edges,
// issuing both row LDG.128s back-to-back so latencies overlap. Tail edges
// carry meta 0 -> u=0, w=0.0f: they read row 0 (valid) and add zero, so the
// inner loop has no per-edge predication.
// ---------------------------------------------------------------------------
__global__ void __launch_bounds__(256) prop_kernel(float* __restrict__ dout, int it)
{
    const float4* __restrict__ hp = (const float4*)
        ((it == 0) ? g_h0 : (((it & 1) == 0) ? g_p1 : g_p0));
    float4* __restrict__ hn = (float4*)
        ((it == KSTEPS - 1) ? dout : (((it & 1) != 0) ? g_p1 : g_p0));
    const float4* __restrict__ h04 = (const float4*)g_h0;

    const int warp = (blockIdx.x * blockDim.x + threadIdx.x) >> 5;
    const int lane = threadIdx.x & 31;
    if (warp >= NNODES) return;
    const int node = warp;

    const int s = g_offs[node];
    const int e = g_offs[node + 1];

    const int grp  = lane / 10;            // 0..2 active, 3 for lanes 30-31
    const int fl   = lane - grp * 10;      // 0..9
    const bool lact = (lane < 30);
    const int src0 = (grp < 3) ? grp : 0;
    const int src1 = src0 + 3;

    float4 acc = make_float4(0.f, 0.f, 0.f, 0.f);

    for (int i = s; i < e; i += 6) {
        long long m = 0;
        if (lane < 6 && (i + lane) < e) m = __ldg(&g_ew[i + lane]);
        const long long m0 = __shfl_sync(0xffffffffu, m, src0);
        const long long m1 = __shfl_sync(0xffffffffu, m, src1);
        const int   u0 = (int)(unsigned)((unsigned long long)m0 & 0xffffffffull);
        const float w0 = __uint_as_float((unsigned)((unsigned long long)m0 >> 32));
        const int   u1 = (int)(unsigned)((unsigned long long)m1 & 0xffffffffull);
        const float w1 = __uint_as_float((unsigned)((unsigned long long)m1 >> 32));
        if (lact) {
            const float4 v0 = __ldg(&hp[(size_t)u0 * 10 + fl]);
            const float4 v1 = __ldg(&hp[(size_t)u1 * 10 + fl]);
            acc.x = fmaf(w0, v0.x, acc.x);
            acc.y = fmaf(w0, v0.y, acc.y);
            acc.z = fmaf(w0, v0.z, acc.z);
            acc.w = fmaf(w0, v0.w, acc.w);
            acc.x = fmaf(w1, v1.x, acc.x);
            acc.y = fmaf(w1, v1.y, acc.y);
            acc.z = fmaf(w1, v1.z, acc.z);
            acc.w = fmaf(w1, v1.w, acc.w);
        }
    }

    // combine the 3 groups into lanes 0-9
    const float t1x = __shfl_sync(0xffffffffu, acc.x, lane + 10);
    const float t1y = __shfl_sync(0xffffffffu, acc.y, lane + 10);
    const float t1z = __shfl_sync(0xffffffffu, acc.z, lane + 10);
    const float t1w = __shfl_sync(0xffffffffu, acc.w, lane + 10);
    const float t2x = __shfl_sync(0xffffffffu, acc.x, lane + 20);
    const float t2y = __shfl_sync(0xffffffffu, acc.y, lane + 20);
    const float t2z = __shfl_sync(0xffffffffu, acc.z, lane + 20);
    const float t2w = __shfl_sync(0xffffffffu, acc.w, lane + 20);

    if (lane < 10) {
        acc.x += t1x + t2x;
        acc.y += t1y + t2y;
        acc.z += t1z + t2z;
        acc.w += t1w + t2w;

        const float d  = g_dinv[node];
        const float sw = d * d;
        const float4 sv = __ldg(&hp[(size_t)node * 10 + lane]);
        const float4 hv = __ldg(&h04[(size_t)node * 10 + lane]);
        float4 o;
        o.x = fmaf(1.0f - ALPHA, fmaf(sw, sv.x, acc.x), ALPHA * hv.x);
        o.y = fmaf(1.0f - ALPHA, fmaf(sw, sv.y, acc.y), ALPHA * hv.y);
        o.z = fmaf(1.0f - ALPHA, fmaf(sw, sv.z, acc.z), ALPHA * hv.z);
        o.w = fmaf(1.0f - ALPHA, fmaf(sw, sv.w, acc.w), ALPHA * hv.w);
        hn[(size_t)node * 10 + lane] = o;
    }
}

// ---------------------------------------------------------------------------
// kernel_launch: ONLY kernel launches. Graph-capturable.
// ---------------------------------------------------------------------------
extern "C" void kernel_launch(void* const* d_in, const int* in_sizes, int n_in,
                              void* d_out, int out_size)
{
    const float* x   = (const float*)d_in[0];
    const int*   ei  = (const int*)d_in[1];   // int32 (JAX x64 disabled)
    const float* W1  = (const float*)d_in[2];
    const float* b1  = (const float*)d_in[3];
    const float* g1  = (const float*)d_in[4];
    const float* be1 = (const float*)d_in[5];
    const float* W2  = (const float*)d_in[6];
    const float* b2  = (const float*)d_in[7];
    const float* g2  = (const float*)d_in[8];
    const float* be2 = (const float*)d_in[9];
    const float* W3  = (const float*)d_in[10];
    const float* b3  = (const float*)d_in[11];
    float*       out = (float*)d_out;

    const int mlp_grid = (NNODES + 63) / 64;

    // --- graph prep + weight pre-split ---
    count_kernel<<<(NEDGES + 255) / 256, 256>>>(ei);                  // 0
    wsplit_kernel<KP1, HID, 0><<<(KP1 * HID + 255) / 256, 256>>>(W1); // 1
    wsplit_kernel<KP2, HID, 1><<<(KP2 * HID + 255) / 256, 256>>>(W2); // 2
    wsplit_kernel<KP2, OUTC, 2><<<(KP2 * OUTC + 255) / 256, 256>>>(W3); // 3
    dinv_kernel<<<(NNODES + 255) / 256, 256>>>();                     // 4
    mlp_mma_kernel<INC, 0, 0><<<mlp_grid, 256>>>(x, b1, g1, be1);     // 5 (ncu)
    scanA_kernel<<<SCAN_NB, 1024>>>();
    scanB_kernel<<<1, 128>>>();
    scanC_kernel<<<SCAN_NB, 1024>>>();
    scatter_kernel<<<(NEDGES + 255) / 256, 256>>>(ei);
    mlp_mma_kernel<HID, 1, 1><<<mlp_grid, 256>>>(nullptr, b2, g2, be2);
    gemm3_mma_kernel<<<(NNODES + 127) / 128, 256>>>(b3);

    // --- APPNP: K steps, ping-pong; last writes d_out ---
    for (int it = 0; it < KSTEPS; ++it)
        prop_kernel<<<(NNODES * 32 + 255) / 256, 256>>>(out, it);

    // restore invariant for next launch
    zero_cnt_kernel<<<(NNODES + 255) / 256, 256>>>();
}